// round 2
// baseline (speedup 1.0000x reference)
#include <cuda_runtime.h>
#include <math.h>

#define NN 50000
#define EE 800000

// ---------------- scratch (device globals, no runtime alloc) ----------------
__device__ int   g_deg[NN];
__device__ int   g_off[NN + 1];
__device__ int   g_cur[NN];
__device__ float g_dinv[NN];
__device__ int   g_srce[EE];
__device__ float g_ew[EE];

__device__ float g_A [(size_t)NN * 128];  // conv1: [init(64) | root(64)]
__device__ float g_B [(size_t)NN * 64];   // conv1 after t=0
__device__ float g_C [(size_t)NN * 64];   // conv1 after deep matmul
__device__ float g_h [(size_t)NN * 32];   // conv1 output (mean over stacks)
__device__ float g_D [(size_t)NN * 160];  // conv2: [init(80) | root(80)]
__device__ float g_E2[(size_t)NN * 80];   // conv2 after t=0
__device__ float g_F2[(size_t)NN * 80];   // conv2 after deep matmul

__device__ float g_Wp1[128 * 128];        // packed [w1_init | w1_root]
__device__ float g_Wd1[64 * 64];          // block-diag w1_deep
__device__ float g_Wp2[32 * 160];         // packed [w2_init | w2_root]
__device__ float g_Wd2[80 * 80];          // block-diag w2_deep

// ---------------- init: zero degree + pack weights (merged) ----------------
__global__ void init_kernel(const float* __restrict__ w1i, const float* __restrict__ w1d,
                            const float* __restrict__ w1r, const float* __restrict__ w2i,
                            const float* __restrict__ w2d, const float* __restrict__ w2r) {
    int i = blockIdx.x * blockDim.x + threadIdx.x;
    if (i < NN) g_deg[i] = 0;
    if (i < 16384) {                       // Wp1 : 128 x 128
        int f = i >> 7, j = i & 127;
        float v;
        if (j < 64) { int k = j >> 5, h = j & 31; v = w1i[(k * 128 + f) * 32 + h]; }
        else        { int j2 = j - 64; int k = j2 >> 5, h = j2 & 31; v = w1r[(k * 128 + f) * 32 + h]; }
        g_Wp1[i] = v;
    } else if (i < 20480) {                // Wd1 : 64 x 64 block-diagonal
        int i2 = i - 16384;
        int g = i2 >> 6, h = i2 & 63;
        int kg = g >> 5, kh = h >> 5;
        g_Wd1[i2] = (kg == kh) ? w1d[(kg * 32 + (g & 31)) * 32 + (h & 31)] : 0.0f;
    } else if (i < 25600) {                // Wp2 : 32 x 160
        int i3 = i - 20480;
        int f = i3 / 160, j = i3 % 160;
        float v;
        if (j < 80) { int k = j / 40, h = j % 40; v = w2i[(k * 32 + f) * 40 + h]; }
        else        { int j2 = j - 80; int k = j2 / 40, h = j2 % 40; v = w2r[(k * 32 + f) * 40 + h]; }
        g_Wp2[i3] = v;
    } else if (i < 32000) {                // Wd2 : 80 x 80 block-diagonal
        int i4 = i - 25600;
        int g = i4 / 80, h = i4 % 80;
        int kg = g / 40, kh = h / 40;
        g_Wd2[i4] = (kg == kh) ? w2d[(kg * 40 + (g % 40)) * 40 + (h % 40)] : 0.0f;
    }
}

__global__ void hist_kernel(const int* __restrict__ col) {
    int i = blockIdx.x * blockDim.x + threadIdx.x;
    if (i < EE) atomicAdd(&g_deg[col[i]], 1);
}

// single-block exclusive scan of g_deg -> g_off; seeds g_cur; computes g_dinv
__global__ void scan_kernel() {
    __shared__ int part[1024];
    const int t = threadIdx.x;
    const int CH = (NN + 1023) / 1024;  // 49
    int base = t * CH;
    int hi = base + CH; if (hi > NN) hi = NN;
    int sum = 0;
    for (int i = base; i < hi; ++i) sum += g_deg[i];
    part[t] = sum;
    __syncthreads();
    for (int off = 1; off < 1024; off <<= 1) {
        int v = (t >= off) ? part[t - off] : 0;
        __syncthreads();
        part[t] += v;
        __syncthreads();
    }
    int run = part[t] - sum;
    for (int i = base; i < hi; ++i) {
        int d = g_deg[i];
        g_off[i] = run;
        g_cur[i] = run;
        g_dinv[i] = (d > 0) ? rsqrtf((float)d) : 0.0f;
        run += d;
    }
    if (t == 1023) g_off[NN] = part[1023];
}

__global__ void fill_kernel(const int* __restrict__ row, const int* __restrict__ col) {
    int i = blockIdx.x * blockDim.x + threadIdx.x;
    if (i < EE) {
        int r = row[i];
        int c = col[i];
        int pos = atomicAdd(&g_cur[c], 1);
        g_srce[pos] = r;
        g_ew[pos]   = g_dinv[r] * g_dinv[c];
    }
}

// ---------------- GEMM: C[N,J] = X[N,F] @ W[F,J] ----------------
// 128x64 tile, 256 threads, 8x4 micro-tile. F must be a multiple of 16.
__global__ void __launch_bounds__(256)
gemm_kernel(const float* __restrict__ X, int ldx,
            const float* __restrict__ W, int ldw,
            float* __restrict__ C, int ldc,
            int nrows, int F, int J) {
    __shared__ float xs[16][132];   // [f][m], padded: bank = (4f+m)%32
    __shared__ float ws[16][64];    // [f][j]

    const int tid = threadIdx.x;
    const int tx  = tid & 15;              // 16 col groups * 4 = 64 cols
    const int ty  = tid >> 4;              // 16 row groups * 8 = 128 rows
    const int n0  = blockIdx.x * 128;
    const int j0  = blockIdx.y * 64;

    float acc[8][4] = {};

    for (int f0 = 0; f0 < F; f0 += 16) {
        // X tile: 128 rows x 16 f, float4 per thread x2, transposed into smem
        #pragma unroll
        for (int l = 0; l < 2; ++l) {
            int idx = tid + l * 256;       // 0..511
            int m = idx >> 2;              // row 0..127
            int fq = idx & 3;              // float4 index
            float4 v = make_float4(0.f, 0.f, 0.f, 0.f);
            if (n0 + m < nrows)
                v = *(const float4*)&X[(size_t)(n0 + m) * ldx + f0 + fq * 4];
            xs[fq * 4 + 0][m] = v.x;
            xs[fq * 4 + 1][m] = v.y;
            xs[fq * 4 + 2][m] = v.z;
            xs[fq * 4 + 3][m] = v.w;
        }
        // W tile: 16 f x 64 j
        #pragma unroll
        for (int l = 0; l < 4; ++l) {
            int idx = tid + l * 256;
            int f = idx >> 6, j = idx & 63;
            ws[f][j] = (j0 + j < J) ? W[(size_t)(f0 + f) * ldw + j0 + j] : 0.0f;
        }
        __syncthreads();
        #pragma unroll
        for (int f = 0; f < 16; ++f) {
            float4 w4 = *(const float4*)&ws[f][tx * 4];
            float4 xa = *(const float4*)&xs[f][ty * 8];
            float4 xb = *(const float4*)&xs[f][ty * 8 + 4];
            acc[0][0] = fmaf(xa.x, w4.x, acc[0][0]); acc[0][1] = fmaf(xa.x, w4.y, acc[0][1]);
            acc[0][2] = fmaf(xa.x, w4.z, acc[0][2]); acc[0][3] = fmaf(xa.x, w4.w, acc[0][3]);
            acc[1][0] = fmaf(xa.y, w4.x, acc[1][0]); acc[1][1] = fmaf(xa.y, w4.y, acc[1][1]);
            acc[1][2] = fmaf(xa.y, w4.z, acc[1][2]); acc[1][3] = fmaf(xa.y, w4.w, acc[1][3]);
            acc[2][0] = fmaf(xa.z, w4.x, acc[2][0]); acc[2][1] = fmaf(xa.z, w4.y, acc[2][1]);
            acc[2][2] = fmaf(xa.z, w4.z, acc[2][2]); acc[2][3] = fmaf(xa.z, w4.w, acc[2][3]);
            acc[3][0] = fmaf(xa.w, w4.x, acc[3][0]); acc[3][1] = fmaf(xa.w, w4.y, acc[3][1]);
            acc[3][2] = fmaf(xa.w, w4.z, acc[3][2]); acc[3][3] = fmaf(xa.w, w4.w, acc[3][3]);
            acc[4][0] = fmaf(xb.x, w4.x, acc[4][0]); acc[4][1] = fmaf(xb.x, w4.y, acc[4][1]);
            acc[4][2] = fmaf(xb.x, w4.z, acc[4][2]); acc[4][3] = fmaf(xb.x, w4.w, acc[4][3]);
            acc[5][0] = fmaf(xb.y, w4.x, acc[5][0]); acc[5][1] = fmaf(xb.y, w4.y, acc[5][1]);
            acc[5][2] = fmaf(xb.y, w4.z, acc[5][2]); acc[5][3] = fmaf(xb.y, w4.w, acc[5][3]);
            acc[6][0] = fmaf(xb.z, w4.x, acc[6][0]); acc[6][1] = fmaf(xb.z, w4.y, acc[6][1]);
            acc[6][2] = fmaf(xb.z, w4.z, acc[6][2]); acc[6][3] = fmaf(xb.z, w4.w, acc[6][3]);
            acc[7][0] = fmaf(xb.w, w4.x, acc[7][0]); acc[7][1] = fmaf(xb.w, w4.y, acc[7][1]);
            acc[7][2] = fmaf(xb.w, w4.z, acc[7][2]); acc[7][3] = fmaf(xb.w, w4.w, acc[7][3]);
        }
        __syncthreads();
    }

    const int jb = j0 + tx * 4;
    #pragma unroll
    for (int r = 0; r < 8; ++r) {
        int n = n0 + ty * 8 + r;
        if (n >= nrows) continue;
        if (jb + 3 < J) {
            *(float4*)&C[(size_t)n * ldc + jb] =
                make_float4(acc[r][0], acc[r][1], acc[r][2], acc[r][3]);
        } else {
            #pragma unroll
            for (int c = 0; c < 4; ++c)
                if (jb + c < J) C[(size_t)n * ldc + jb + c] = acc[r][c];
        }
    }
}

// ---------------- CSR propagate: gather + root + bias (+relu / +mean / +lsm) --------
// FTOT = 2 stacks * F_out (64 or 80). Warp per node.
template <int FTOT, bool RELU, bool FINAL, bool LSM>
__global__ void prop_kernel(const float* __restrict__ src, int lds,
                            const float* __restrict__ root, int ldr,
                            const float* __restrict__ bias,
                            float* __restrict__ out, int ldo) {
    const int gwarp = (blockIdx.x * blockDim.x + threadIdx.x) >> 5;
    const int lane  = threadIdx.x & 31;
    if (gwarp >= NN) return;
    const int n   = gwarp;
    const int beg = g_off[n];
    const int end = g_off[n + 1];

    float a0 = 0.f, a1 = 0.f, a2 = 0.f;
    int e = beg;
    for (; e + 4 <= end; e += 4) {             // 4-edge unroll for MLP
        int   s0 = g_srce[e],     s1 = g_srce[e + 1];
        int   s2 = g_srce[e + 2], s3 = g_srce[e + 3];
        float w0 = g_ew[e],       w1 = g_ew[e + 1];
        float w2 = g_ew[e + 2],   w3 = g_ew[e + 3];
        const float* p0 = src + (size_t)s0 * lds;
        const float* p1 = src + (size_t)s1 * lds;
        const float* p2 = src + (size_t)s2 * lds;
        const float* p3 = src + (size_t)s3 * lds;
        float u0 = p0[lane],      u1 = p1[lane],      u2 = p2[lane],      u3 = p3[lane];
        float v0 = p0[lane + 32], v1 = p1[lane + 32], v2 = p2[lane + 32], v3 = p3[lane + 32];
        a0 = fmaf(w0, u0, a0); a0 = fmaf(w1, u1, a0);
        a0 = fmaf(w2, u2, a0); a0 = fmaf(w3, u3, a0);
        a1 = fmaf(w0, v0, a1); a1 = fmaf(w1, v1, a1);
        a1 = fmaf(w2, v2, a1); a1 = fmaf(w3, v3, a1);
        if (FTOT == 80) {
            if (lane < 16) {
                float t0 = p0[lane + 64], t1 = p1[lane + 64];
                float t2 = p2[lane + 64], t3 = p3[lane + 64];
                a2 = fmaf(w0, t0, a2); a2 = fmaf(w1, t1, a2);
                a2 = fmaf(w2, t2, a2); a2 = fmaf(w3, t3, a2);
            }
        }
    }
    for (; e < end; ++e) {
        int   s0 = g_srce[e];
        float w0 = g_ew[e];
        const float* p0 = src + (size_t)s0 * lds;
        a0 = fmaf(w0, p0[lane], a0);
        a1 = fmaf(w0, p0[lane + 32], a1);
        if (FTOT == 80) { if (lane < 16) a2 = fmaf(w0, p0[lane + 64], a2); }
    }

    const float* rp = root + (size_t)n * ldr;
    float y0 = a0 + rp[lane]      + bias[lane];
    float y1 = a1 + rp[lane + 32] + bias[lane + 32];
    float y2 = 0.f;
    if (FTOT == 80 && lane < 16) y2 = a2 + rp[lane + 64] + bias[lane + 64];
    if (RELU) { y0 = fmaxf(y0, 0.f); y1 = fmaxf(y1, 0.f); y2 = fmaxf(y2, 0.f); }

    if (!FINAL) {
        float* op = out + (size_t)n * ldo;
        op[lane] = y0;
        op[lane + 32] = y1;
        if (FTOT == 80) { if (lane < 16) op[lane + 64] = y2; }
        return;
    }

    if (FTOT == 64) {
        // mean over stacks: cols [0,32) and [32,64) pair up per lane
        out[(size_t)n * 32 + lane] = 0.5f * (y0 + y1);
    } else {
        // FTOT=80, F_out=40: mean[h] = 0.5*(v[h] + v[40+h])
        // lanes: y0 = v[lane], y1 = v[32+lane], y2 = v[64+lane] (lane<16)
        float t1 = __shfl_sync(0xffffffffu, y1, (lane + 8) & 31);   // v[40+lane], lane<24
        float t2 = __shfl_sync(0xffffffffu, y2, (lane - 24) & 31);  // v[40+lane], lane>=24
        float m0 = 0.5f * (y0 + ((lane < 24) ? t1 : t2));           // mean cols 0..31
        float t3 = __shfl_sync(0xffffffffu, y2, (lane + 8) & 31);   // v[72+lane]
        float m1 = 0.5f * (y1 + t3);                                // mean cols 32..39 (lane<8)
        if (!LSM) {
            out[(size_t)n * 40 + lane] = m0;
            if (lane < 8) out[(size_t)n * 40 + 32 + lane] = m1;
        } else {
            float mv = fmaxf(m0, (lane < 8) ? m1 : -3.0e38f);
            #pragma unroll
            for (int o = 16; o; o >>= 1) mv = fmaxf(mv, __shfl_xor_sync(0xffffffffu, mv, o));
            float s = expf(m0 - mv) + ((lane < 8) ? expf(m1 - mv) : 0.0f);
            #pragma unroll
            for (int o = 16; o; o >>= 1) s += __shfl_xor_sync(0xffffffffu, s, o);
            float l = mv + logf(s);
            out[(size_t)n * 40 + lane] = m0 - l;
            if (lane < 8) out[(size_t)n * 40 + 32 + lane] = m1 - l;
        }
    }
}

// ---------------- launch ----------------
extern "C" void kernel_launch(void* const* d_in, const int* in_sizes, int n_in,
                              void* d_out, int out_size) {
    const float* x    = (const float*)d_in[0];
    const int*   eidx = (const int*)  d_in[1];
    const float* w1i  = (const float*)d_in[2];
    const float* w1d  = (const float*)d_in[3];
    const float* w1r  = (const float*)d_in[4];
    const float* b1   = (const float*)d_in[5];
    const float* w2i  = (const float*)d_in[6];
    const float* w2d  = (const float*)d_in[7];
    const float* w2r  = (const float*)d_in[8];
    const float* b2   = (const float*)d_in[9];
    float* outp = (float*)d_out;

    const int* row = eidx;
    const int* col = eidx + EE;

    float *A, *B, *C, *H, *D, *E2, *F2, *Wp1, *Wd1, *Wp2, *Wd2;
    cudaGetSymbolAddress((void**)&A,   g_A);
    cudaGetSymbolAddress((void**)&B,   g_B);
    cudaGetSymbolAddress((void**)&C,   g_C);
    cudaGetSymbolAddress((void**)&H,   g_h);
    cudaGetSymbolAddress((void**)&D,   g_D);
    cudaGetSymbolAddress((void**)&E2,  g_E2);
    cudaGetSymbolAddress((void**)&F2,  g_F2);
    cudaGetSymbolAddress((void**)&Wp1, g_Wp1);
    cudaGetSymbolAddress((void**)&Wd1, g_Wd1);
    cudaGetSymbolAddress((void**)&Wp2, g_Wp2);
    cudaGetSymbolAddress((void**)&Wd2, g_Wd2);

    const int TB = 256;
    const int nblkE = (EE + TB - 1) / TB;            // 3125
    const int nblkW = (NN * 32 + TB - 1) / TB;       // 6250 (warp per node)
    const int gR = (NN + 127) / 128;                 // 391 row tiles

    // graph prep + weight packing
    init_kernel<<<(NN + TB - 1) / TB, TB>>>(w1i, w1d, w1r, w2i, w2d, w2r);
    hist_kernel<<<nblkE, TB>>>(col);
    scan_kernel<<<1, 1024>>>();
    fill_kernel<<<nblkE, TB>>>(row, col);

    // ---- conv1 ----
    gemm_kernel<<<dim3(gR, 2), TB>>>(x, 128, Wp1, 128, A, 128, NN, 128, 128);
    prop_kernel<64, true, false, false><<<nblkW, TB>>>(A, 128, A + 64, 128, b1, B, 64);
    gemm_kernel<<<dim3(gR, 1), TB>>>(B, 64, Wd1, 64, C, 64, NN, 64, 64);
    prop_kernel<64, true, true, false><<<nblkW, TB>>>(C, 64, A + 64, 128, b1, H, 32);

    // ---- conv2 ----
    gemm_kernel<<<dim3(gR, 3), TB>>>(H, 32, Wp2, 160, D, 160, NN, 32, 160);
    prop_kernel<80, false, false, false><<<nblkW, TB>>>(D, 160, D + 80, 160, b2, E2, 80);
    gemm_kernel<<<dim3(gR, 2), TB>>>(E2, 80, Wd2, 80, F2, 80, NN, 80, 80);
    prop_kernel<80, false, true, true><<<nblkW, TB>>>(F2, 80, D + 80, 160, b2, outp, 40);
}

// round 3
// speedup vs baseline: 1.1569x; 1.1569x over previous
#include <cuda_runtime.h>
#include <math.h>

#define NN 50000
#define EE 800000

// ---------------- scratch (device globals, no runtime alloc) ----------------
__device__ int   g_deg[NN];
__device__ int   g_off[NN + 1];
__device__ int   g_cur[NN];
__device__ float g_dinv[NN];
__device__ int   g_srce[EE];
__device__ float g_ew[EE];

__device__ float g_A [(size_t)NN * 128];  // conv1: [init(64) | root(64)]
__device__ float g_B [(size_t)NN * 64];   // conv1 after t=0
__device__ float g_C [(size_t)NN * 64];   // conv1 deep matmul out
__device__ float g_HH[(size_t)NN * 64];   // [PH(32) | H(32)]
__device__ float g_D [(size_t)NN * 80];   // [G(40) | Rm(40)]

__device__ float g_Wp1[128 * 128];        // packed [w1_init | w1_root]
__device__ float g_W3 [64 * 80];          // folded conv2 weights
__device__ float g_b3 [80];               // folded conv2 bias

// ---------------- init: zero degree + pack Wp1 + fold conv2 weights ----------------
__global__ void init_kernel(const float* __restrict__ w1i, const float* __restrict__ w1r,
                            const float* __restrict__ w2i, const float* __restrict__ w2d,
                            const float* __restrict__ w2r, const float* __restrict__ b2) {
    int i = blockIdx.x * blockDim.x + threadIdx.x;
    if (i < NN) g_deg[i] = 0;
    if (i < 16384) {                       // Wp1 : 128 x 128 = [w1_init | w1_root]
        int f = i >> 7, j = i & 127;
        float v;
        if (j < 64) { int k = j >> 5, h = j & 31; v = w1i[(k * 128 + f) * 32 + h]; }
        else        { int j2 = j - 64; int k = j2 >> 5, h = j2 & 31; v = w1r[(k * 128 + f) * 32 + h]; }
        g_Wp1[i] = v;
    } else if (i < 16384 + 64 * 80 + 80) {
        int i2 = i - 16384;
        if (i2 < 64 * 80) {
            // W3[f][g]:  f<32 -> PH row,  f>=32 -> H row
            //   g<40:  G   = 0.5 * sum_k (w_in/w_root)_k @ w_deep_k
            //   g>=40: Rm  = 0.5 * sum_k w_root_k          (PH rows zero)
            int f = i2 / 80, g = i2 % 80;
            float v = 0.0f;
            if (g < 40) {
                const float* wa = (f < 32) ? w2i : w2r;
                int fr = (f < 32) ? f : f - 32;
                #pragma unroll
                for (int k = 0; k < 2; ++k) {
                    float s = 0.0f;
                    for (int j = 0; j < 40; ++j)
                        s = fmaf(wa[(k * 32 + fr) * 40 + j], w2d[(k * 40 + j) * 40 + g], s);
                    v += s;
                }
                v *= 0.5f;
            } else if (f >= 32) {
                int fr = f - 32, gg = g - 40;
                v = 0.5f * (w2r[(0 * 32 + fr) * 40 + gg] + w2r[(1 * 32 + fr) * 40 + gg]);
            }
            g_W3[i2] = v;
        } else {
            int g = i2 - 64 * 80;          // bias3
            float v;
            if (g < 40) {
                v = 0.0f;
                #pragma unroll
                for (int k = 0; k < 2; ++k)
                    for (int j = 0; j < 40; ++j)
                        v = fmaf(b2[k * 40 + j], w2d[(k * 40 + j) * 40 + g], v);
                v *= 0.5f;
            } else {
                v = 0.5f * (b2[g - 40] + b2[40 + g - 40]);
            }
            g_b3[g] = v;
        }
    }
}

__global__ void hist_kernel(const int* __restrict__ col) {
    int i = blockIdx.x * blockDim.x + threadIdx.x;
    if (i < EE) atomicAdd(&g_deg[col[i]], 1);
}

// single-block exclusive scan of g_deg -> g_off; seeds g_cur; computes g_dinv
__global__ void scan_kernel() {
    __shared__ int part[1024];
    const int t = threadIdx.x;
    const int CH = (NN + 1023) / 1024;  // 49
    int base = t * CH;
    int hi = base + CH; if (hi > NN) hi = NN;
    int sum = 0;
    for (int i = base; i < hi; ++i) sum += g_deg[i];
    part[t] = sum;
    __syncthreads();
    for (int off = 1; off < 1024; off <<= 1) {
        int v = (t >= off) ? part[t - off] : 0;
        __syncthreads();
        part[t] += v;
        __syncthreads();
    }
    int run = part[t] - sum;
    for (int i = base; i < hi; ++i) {
        int d = g_deg[i];
        g_off[i] = run;
        g_cur[i] = run;
        g_dinv[i] = (d > 0) ? rsqrtf((float)d) : 0.0f;
        run += d;
    }
    if (t == 1023) g_off[NN] = part[1023];
}

__global__ void fill_kernel(const int* __restrict__ row, const int* __restrict__ col) {
    int i = blockIdx.x * blockDim.x + threadIdx.x;
    if (i < EE) {
        int r = row[i];
        int c = col[i];
        int pos = atomicAdd(&g_cur[c], 1);
        g_srce[pos] = r;
        g_ew[pos]   = g_dinv[r] * g_dinv[c];
    }
}

// ---------------- GEMM 128x64 tile (used for GEMM1, J multiple of 4) ----------------
__global__ void __launch_bounds__(256)
gemm_kernel(const float* __restrict__ X, int ldx,
            const float* __restrict__ W, int ldw,
            float* __restrict__ C, int ldc,
            int nrows, int F, int J) {
    __shared__ float xs[16][132];
    __shared__ float ws[16][64];

    const int tid = threadIdx.x;
    const int tx  = tid & 15;
    const int ty  = tid >> 4;
    const int n0  = blockIdx.x * 128;
    const int j0  = blockIdx.y * 64;

    float acc[8][4] = {};

    for (int f0 = 0; f0 < F; f0 += 16) {
        #pragma unroll
        for (int l = 0; l < 2; ++l) {
            int idx = tid + l * 256;
            int m = idx >> 2;
            int fq = idx & 3;
            float4 v = make_float4(0.f, 0.f, 0.f, 0.f);
            if (n0 + m < nrows)
                v = *(const float4*)&X[(size_t)(n0 + m) * ldx + f0 + fq * 4];
            xs[fq * 4 + 0][m] = v.x;
            xs[fq * 4 + 1][m] = v.y;
            xs[fq * 4 + 2][m] = v.z;
            xs[fq * 4 + 3][m] = v.w;
        }
        #pragma unroll
        for (int l = 0; l < 4; ++l) {
            int idx = tid + l * 256;
            int f = idx >> 6, j = idx & 63;
            ws[f][j] = (j0 + j < J) ? W[(size_t)(f0 + f) * ldw + j0 + j] : 0.0f;
        }
        __syncthreads();
        #pragma unroll
        for (int f = 0; f < 16; ++f) {
            float4 w4 = *(const float4*)&ws[f][tx * 4];
            float4 xa = *(const float4*)&xs[f][ty * 8];
            float4 xb = *(const float4*)&xs[f][ty * 8 + 4];
            acc[0][0] = fmaf(xa.x, w4.x, acc[0][0]); acc[0][1] = fmaf(xa.x, w4.y, acc[0][1]);
            acc[0][2] = fmaf(xa.x, w4.z, acc[0][2]); acc[0][3] = fmaf(xa.x, w4.w, acc[0][3]);
            acc[1][0] = fmaf(xa.y, w4.x, acc[1][0]); acc[1][1] = fmaf(xa.y, w4.y, acc[1][1]);
            acc[1][2] = fmaf(xa.y, w4.z, acc[1][2]); acc[1][3] = fmaf(xa.y, w4.w, acc[1][3]);
            acc[2][0] = fmaf(xa.z, w4.x, acc[2][0]); acc[2][1] = fmaf(xa.z, w4.y, acc[2][1]);
            acc[2][2] = fmaf(xa.z, w4.z, acc[2][2]); acc[2][3] = fmaf(xa.z, w4.w, acc[2][3]);
            acc[3][0] = fmaf(xa.w, w4.x, acc[3][0]); acc[3][1] = fmaf(xa.w, w4.y, acc[3][1]);
            acc[3][2] = fmaf(xa.w, w4.z, acc[3][2]); acc[3][3] = fmaf(xa.w, w4.w, acc[3][3]);
            acc[4][0] = fmaf(xb.x, w4.x, acc[4][0]); acc[4][1] = fmaf(xb.x, w4.y, acc[4][1]);
            acc[4][2] = fmaf(xb.x, w4.z, acc[4][2]); acc[4][3] = fmaf(xb.x, w4.w, acc[4][3]);
            acc[5][0] = fmaf(xb.y, w4.x, acc[5][0]); acc[5][1] = fmaf(xb.y, w4.y, acc[5][1]);
            acc[5][2] = fmaf(xb.y, w4.z, acc[5][2]); acc[5][3] = fmaf(xb.y, w4.w, acc[5][3]);
            acc[6][0] = fmaf(xb.z, w4.x, acc[6][0]); acc[6][1] = fmaf(xb.z, w4.y, acc[6][1]);
            acc[6][2] = fmaf(xb.z, w4.z, acc[6][2]); acc[6][3] = fmaf(xb.z, w4.w, acc[6][3]);
            acc[7][0] = fmaf(xb.w, w4.x, acc[7][0]); acc[7][1] = fmaf(xb.w, w4.y, acc[7][1]);
            acc[7][2] = fmaf(xb.w, w4.z, acc[7][2]); acc[7][3] = fmaf(xb.w, w4.w, acc[7][3]);
        }
        __syncthreads();
    }

    const int jb = j0 + tx * 4;
    #pragma unroll
    for (int r = 0; r < 8; ++r) {
        int n = n0 + ty * 8 + r;
        if (n >= nrows) continue;
        if (jb + 3 < J) {
            *(float4*)&C[(size_t)n * ldc + jb] =
                make_float4(acc[r][0], acc[r][1], acc[r][2], acc[r][3]);
        } else {
            #pragma unroll
            for (int c = 0; c < 4; ++c)
                if (jb + c < J) C[(size_t)n * ldc + jb + c] = acc[r][c];
        }
    }
}

// ---------------- GEMM 128x32 tile (small-J GEMMs), optional bias ----------------
__global__ void __launch_bounds__(256)
gemm32_kernel(const float* __restrict__ X, int ldx,
              const float* __restrict__ W, int ldw,
              const float* __restrict__ bias,
              float* __restrict__ C, int ldc,
              int nrows, int F, int J) {
    __shared__ float xs[16][132];
    __shared__ float ws[16][32];

    const int tid = threadIdx.x;
    const int tx  = tid & 7;               // 8 * 4 = 32 cols
    const int ty  = tid >> 3;              // 32 * 4 = 128 rows
    const int n0  = blockIdx.x * 128;
    const int j0  = blockIdx.y * 32;

    float acc[4][4] = {};

    for (int f0 = 0; f0 < F; f0 += 16) {
        #pragma unroll
        for (int l = 0; l < 2; ++l) {
            int idx = tid + l * 256;
            int m = idx >> 2;
            int fq = idx & 3;
            float4 v = make_float4(0.f, 0.f, 0.f, 0.f);
            if (n0 + m < nrows)
                v = *(const float4*)&X[(size_t)(n0 + m) * ldx + f0 + fq * 4];
            xs[fq * 4 + 0][m] = v.x;
            xs[fq * 4 + 1][m] = v.y;
            xs[fq * 4 + 2][m] = v.z;
            xs[fq * 4 + 3][m] = v.w;
        }
        #pragma unroll
        for (int l = 0; l < 2; ++l) {
            int idx = tid + l * 256;       // 0..511
            int f = idx >> 5, j = idx & 31;
            ws[f][j] = (j0 + j < J) ? W[(size_t)(f0 + f) * ldw + j0 + j] : 0.0f;
        }
        __syncthreads();
        #pragma unroll
        for (int f = 0; f < 16; ++f) {
            float4 w4 = *(const float4*)&ws[f][tx * 4];
            float4 xa = *(const float4*)&xs[f][ty * 4];
            acc[0][0] = fmaf(xa.x, w4.x, acc[0][0]); acc[0][1] = fmaf(xa.x, w4.y, acc[0][1]);
            acc[0][2] = fmaf(xa.x, w4.z, acc[0][2]); acc[0][3] = fmaf(xa.x, w4.w, acc[0][3]);
            acc[1][0] = fmaf(xa.y, w4.x, acc[1][0]); acc[1][1] = fmaf(xa.y, w4.y, acc[1][1]);
            acc[1][2] = fmaf(xa.y, w4.z, acc[1][2]); acc[1][3] = fmaf(xa.y, w4.w, acc[1][3]);
            acc[2][0] = fmaf(xa.z, w4.x, acc[2][0]); acc[2][1] = fmaf(xa.z, w4.y, acc[2][1]);
            acc[2][2] = fmaf(xa.z, w4.z, acc[2][2]); acc[2][3] = fmaf(xa.z, w4.w, acc[2][3]);
            acc[3][0] = fmaf(xa.w, w4.x, acc[3][0]); acc[3][1] = fmaf(xa.w, w4.y, acc[3][1]);
            acc[3][2] = fmaf(xa.w, w4.z, acc[3][2]); acc[3][3] = fmaf(xa.w, w4.w, acc[3][3]);
        }
        __syncthreads();
    }

    const int jb = j0 + tx * 4;
    float bv[4] = {0.f, 0.f, 0.f, 0.f};
    if (bias) {
        #pragma unroll
        for (int c = 0; c < 4; ++c)
            if (jb + c < J) bv[c] = bias[jb + c];
    }
    #pragma unroll
    for (int r = 0; r < 4; ++r) {
        int n = n0 + ty * 4 + r;
        if (n >= nrows) continue;
        if (jb + 3 < J) {
            *(float4*)&C[(size_t)n * ldc + jb] =
                make_float4(acc[r][0] + bv[0], acc[r][1] + bv[1],
                            acc[r][2] + bv[2], acc[r][3] + bv[3]);
        } else {
            #pragma unroll
            for (int c = 0; c < 4; ++c)
                if (jb + c < J) C[(size_t)n * ldc + jb + c] = acc[r][c] + bv[c];
        }
    }
}

// ---------------- width-64 propagate (conv1): gather + root + bias + relu (+mean) ----
template <bool FINAL>
__global__ void prop64_kernel(const float* __restrict__ src, int lds,
                              const float* __restrict__ root, int ldr,
                              const float* __restrict__ bias,
                              float* __restrict__ out, int ldo) {
    const int gwarp = (blockIdx.x * blockDim.x + threadIdx.x) >> 5;
    const int lane  = threadIdx.x & 31;
    if (gwarp >= NN) return;
    const int n   = gwarp;
    const int beg = g_off[n];
    const int end = g_off[n + 1];

    float a0 = 0.f, a1 = 0.f;
    int e = beg;
    for (; e + 4 <= end; e += 4) {
        int   s0 = g_srce[e],     s1 = g_srce[e + 1];
        int   s2 = g_srce[e + 2], s3 = g_srce[e + 3];
        float w0 = g_ew[e],       w1 = g_ew[e + 1];
        float w2 = g_ew[e + 2],   w3 = g_ew[e + 3];
        const float* p0 = src + (size_t)s0 * lds;
        const float* p1 = src + (size_t)s1 * lds;
        const float* p2 = src + (size_t)s2 * lds;
        const float* p3 = src + (size_t)s3 * lds;
        float u0 = p0[lane],      u1 = p1[lane],      u2 = p2[lane],      u3 = p3[lane];
        float v0 = p0[lane + 32], v1 = p1[lane + 32], v2 = p2[lane + 32], v3 = p3[lane + 32];
        a0 = fmaf(w0, u0, a0); a0 = fmaf(w1, u1, a0);
        a0 = fmaf(w2, u2, a0); a0 = fmaf(w3, u3, a0);
        a1 = fmaf(w0, v0, a1); a1 = fmaf(w1, v1, a1);
        a1 = fmaf(w2, v2, a1); a1 = fmaf(w3, v3, a1);
    }
    for (; e < end; ++e) {
        int   s0 = g_srce[e];
        float w0 = g_ew[e];
        const float* p0 = src + (size_t)s0 * lds;
        a0 = fmaf(w0, p0[lane], a0);
        a1 = fmaf(w0, p0[lane + 32], a1);
    }

    const float* rp = root + (size_t)n * ldr;
    float y0 = fmaxf(a0 + rp[lane]      + bias[lane],      0.f);
    float y1 = fmaxf(a1 + rp[lane + 32] + bias[lane + 32], 0.f);

    if (!FINAL) {
        float* op = out + (size_t)n * ldo;
        op[lane] = y0;
        op[lane + 32] = y1;
    } else {
        out[(size_t)n * ldo + lane] = 0.5f * (y0 + y1);   // mean over the 2 stacks
    }
}

// ---------------- width-32 pure gather: PH = A(H) ----------------
__global__ void prop32_kernel(const float* __restrict__ src, int lds,
                              float* __restrict__ out, int ldo) {
    const int gwarp = (blockIdx.x * blockDim.x + threadIdx.x) >> 5;
    const int lane  = threadIdx.x & 31;
    if (gwarp >= NN) return;
    const int n   = gwarp;
    const int beg = g_off[n];
    const int end = g_off[n + 1];

    float a0 = 0.f;
    int e = beg;
    for (; e + 4 <= end; e += 4) {
        int   s0 = g_srce[e],     s1 = g_srce[e + 1];
        int   s2 = g_srce[e + 2], s3 = g_srce[e + 3];
        float w0 = g_ew[e],       w1 = g_ew[e + 1];
        float w2 = g_ew[e + 2],   w3 = g_ew[e + 3];
        float u0 = src[(size_t)s0 * lds + lane];
        float u1 = src[(size_t)s1 * lds + lane];
        float u2 = src[(size_t)s2 * lds + lane];
        float u3 = src[(size_t)s3 * lds + lane];
        a0 = fmaf(w0, u0, a0); a0 = fmaf(w1, u1, a0);
        a0 = fmaf(w2, u2, a0); a0 = fmaf(w3, u3, a0);
    }
    for (; e < end; ++e)
        a0 = fmaf(g_ew[e], src[(size_t)g_srce[e] * lds + lane], a0);
    out[(size_t)n * ldo + lane] = a0;
}

// ---------------- width-40 final propagate + log_softmax ----------------
__global__ void prop40_kernel(const float* __restrict__ src, int lds,   // G at ld 80
                              const float* __restrict__ root, int ldr,  // Rm+bm at ld 80
                              float* __restrict__ out) {
    const int gwarp = (blockIdx.x * blockDim.x + threadIdx.x) >> 5;
    const int lane  = threadIdx.x & 31;
    if (gwarp >= NN) return;
    const int n   = gwarp;
    const int beg = g_off[n];
    const int end = g_off[n + 1];

    float a0 = 0.f, a1 = 0.f;
    int e = beg;
    for (; e + 4 <= end; e += 4) {
        int   s0 = g_srce[e],     s1 = g_srce[e + 1];
        int   s2 = g_srce[e + 2], s3 = g_srce[e + 3];
        float w0 = g_ew[e],       w1 = g_ew[e + 1];
        float w2 = g_ew[e + 2],   w3 = g_ew[e + 3];
        const float* p0 = src + (size_t)s0 * lds;
        const float* p1 = src + (size_t)s1 * lds;
        const float* p2 = src + (size_t)s2 * lds;
        const float* p3 = src + (size_t)s3 * lds;
        a0 = fmaf(w0, p0[lane], a0); a0 = fmaf(w1, p1[lane], a0);
        a0 = fmaf(w2, p2[lane], a0); a0 = fmaf(w3, p3[lane], a0);
        if (lane < 8) {
            a1 = fmaf(w0, p0[lane + 32], a1); a1 = fmaf(w1, p1[lane + 32], a1);
            a1 = fmaf(w2, p2[lane + 32], a1); a1 = fmaf(w3, p3[lane + 32], a1);
        }
    }
    for (; e < end; ++e) {
        float w0 = g_ew[e];
        const float* p0 = src + (size_t)g_srce[e] * lds;
        a0 = fmaf(w0, p0[lane], a0);
        if (lane < 8) a1 = fmaf(w0, p0[lane + 32], a1);
    }

    const float* rp = root + (size_t)n * ldr;
    float m0 = a0 + rp[lane];
    float m1 = (lane < 8) ? (a1 + rp[lane + 32]) : -3.0e38f;

    float mv = fmaxf(m0, m1);
    #pragma unroll
    for (int o = 16; o; o >>= 1) mv = fmaxf(mv, __shfl_xor_sync(0xffffffffu, mv, o));
    float s = expf(m0 - mv) + ((lane < 8) ? expf(m1 - mv) : 0.0f);
    #pragma unroll
    for (int o = 16; o; o >>= 1) s += __shfl_xor_sync(0xffffffffu, s, o);
    float l = mv + logf(s);
    out[(size_t)n * 40 + lane] = m0 - l;
    if (lane < 8) out[(size_t)n * 40 + 32 + lane] = m1 - l;
}

// ---------------- launch ----------------
extern "C" void kernel_launch(void* const* d_in, const int* in_sizes, int n_in,
                              void* d_out, int out_size) {
    const float* x    = (const float*)d_in[0];
    const int*   eidx = (const int*)  d_in[1];
    const float* w1i  = (const float*)d_in[2];
    const float* w1d  = (const float*)d_in[3];
    const float* w1r  = (const float*)d_in[4];
    const float* b1   = (const float*)d_in[5];
    const float* w2i  = (const float*)d_in[6];
    const float* w2d  = (const float*)d_in[7];
    const float* w2r  = (const float*)d_in[8];
    const float* b2   = (const float*)d_in[9];
    float* outp = (float*)d_out;

    const int* row = eidx;
    const int* col = eidx + EE;

    float *A, *B, *C, *HH, *D, *Wp1, *W3, *b3;
    cudaGetSymbolAddress((void**)&A,   g_A);
    cudaGetSymbolAddress((void**)&B,   g_B);
    cudaGetSymbolAddress((void**)&C,   g_C);
    cudaGetSymbolAddress((void**)&HH,  g_HH);
    cudaGetSymbolAddress((void**)&D,   g_D);
    cudaGetSymbolAddress((void**)&Wp1, g_Wp1);
    cudaGetSymbolAddress((void**)&W3,  g_W3);
    cudaGetSymbolAddress((void**)&b3,  g_b3);

    const int TB = 256;
    const int nblkE = (EE + TB - 1) / TB;            // 3125
    const int nblkW = (NN * 32 + TB - 1) / TB;       // 6250 (warp per node)
    const int gR = (NN + 127) / 128;                 // 391 row tiles

    // graph prep + weight packing / folding
    init_kernel<<<(NN + TB - 1) / TB, TB>>>(w1i, w1r, w2i, w2d, w2r, b2);
    hist_kernel<<<nblkE, TB>>>(col);
    scan_kernel<<<1, 1024>>>();
    fill_kernel<<<nblkE, TB>>>(row, col);

    // ---- conv1 ----
    gemm_kernel<<<dim3(gR, 2), TB>>>(x, 128, Wp1, 128, A, 128, NN, 128, 128);
    prop64_kernel<false><<<nblkW, TB>>>(A, 128, A + 64, 128, b1, B, 64);
    // block-diagonal deep matmul: two true 32x32 GEMMs (no zero padding)
    gemm32_kernel<<<dim3(gR, 1), TB>>>(B,      64, w1d,        32, nullptr, C,      64, NN, 32, 32);
    gemm32_kernel<<<dim3(gR, 1), TB>>>(B + 32, 64, w1d + 1024, 32, nullptr, C + 32, 64, NN, 32, 32);
    prop64_kernel<true><<<nblkW, TB>>>(C, 64, A + 64, 128, b1, HH + 32, 64);  // H -> cols 32..63

    // ---- conv2 (algebraically folded) ----
    prop32_kernel<<<nblkW, TB>>>(HH + 32, 64, HH, 64);                        // PH -> cols 0..31
    gemm32_kernel<<<dim3(gR, 3), TB>>>(HH, 64, W3, 80, b3, D, 80, NN, 64, 80); // [G | Rm+bm]
    prop40_kernel<<<nblkW, TB>>>(D, 80, D + 40, 80, outp);
}

// round 4
// speedup vs baseline: 1.1751x; 1.0157x over previous
#include <cuda_runtime.h>
#include <math.h>

#define NN 50000
#define EE 800000

typedef unsigned long long u64;

// ---------------- f32x2 packed-FMA helpers (bit-identical fp32) ----------------
__device__ __forceinline__ u64 pack2(float lo, float hi) {
    u64 r; asm("mov.b64 %0, {%1, %2};" : "=l"(r) : "f"(lo), "f"(hi)); return r;
}
__device__ __forceinline__ void ffma2(u64& d, u64 a, u64 b) {
    asm("fma.rn.f32x2 %0, %1, %2, %0;" : "+l"(d) : "l"(a), "l"(b));
}
__device__ __forceinline__ float2 unpack2(u64 v) {
    float2 f; asm("mov.b64 {%0, %1}, %2;" : "=f"(f.x), "=f"(f.y) : "l"(v)); return f;
}

// ---------------- scratch (device globals, no runtime alloc) ----------------
__device__ int   g_deg[NN];
__device__ int   g_off[NN + 1];
__device__ int   g_cur[NN];
__device__ float g_dinv[NN];
__device__ int   g_srce[EE];
__device__ float g_ew[EE];

__device__ float g_A [(size_t)NN * 128];  // conv1: [init(64) | root+b1(64)]
__device__ float g_B [(size_t)NN * 64];   // conv1 after t=0
__device__ float g_C [(size_t)NN * 64];   // conv1 deep matmul out
__device__ float g_HH[(size_t)NN * 64];   // [PH(32) | H(32)]
__device__ float g_D [(size_t)NN * 80];   // [G(40) | Rm+bm(40)]

__device__ float g_Wp1[128 * 128];        // packed [w1_init | w1_root]
__device__ float g_W3 [64 * 80];          // folded conv2 weights
__device__ float g_b3 [80];               // folded conv2 bias

// ---------------- init: zero degree + pack Wp1 + fold conv2 weights ----------------
__global__ void init_kernel(const float* __restrict__ w1i, const float* __restrict__ w1r,
                            const float* __restrict__ w2i, const float* __restrict__ w2d,
                            const float* __restrict__ w2r, const float* __restrict__ b2) {
    int i = blockIdx.x * blockDim.x + threadIdx.x;
    if (i < NN) g_deg[i] = 0;
    if (i < 16384) {                       // Wp1 : 128 x 128 = [w1_init | w1_root]
        int f = i >> 7, j = i & 127;
        float v;
        if (j < 64) { int k = j >> 5, h = j & 31; v = w1i[(k * 128 + f) * 32 + h]; }
        else        { int j2 = j - 64; int k = j2 >> 5, h = j2 & 31; v = w1r[(k * 128 + f) * 32 + h]; }
        g_Wp1[i] = v;
    } else if (i < 16384 + 64 * 80 + 80) {
        int i2 = i - 16384;
        if (i2 < 64 * 80) {
            int f = i2 / 80, g = i2 % 80;
            float v = 0.0f;
            if (g < 40) {
                const float* wa = (f < 32) ? w2i : w2r;
                int fr = (f < 32) ? f : f - 32;
                #pragma unroll
                for (int k = 0; k < 2; ++k) {
                    float s = 0.0f;
                    for (int j = 0; j < 40; ++j)
                        s = fmaf(wa[(k * 32 + fr) * 40 + j], w2d[(k * 40 + j) * 40 + g], s);
                    v += s;
                }
                v *= 0.5f;
            } else if (f >= 32) {
                int fr = f - 32, gg = g - 40;
                v = 0.5f * (w2r[(0 * 32 + fr) * 40 + gg] + w2r[(1 * 32 + fr) * 40 + gg]);
            }
            g_W3[i2] = v;
        } else {
            int g = i2 - 64 * 80;
            float v;
            if (g < 40) {
                v = 0.0f;
                #pragma unroll
                for (int k = 0; k < 2; ++k)
                    for (int j = 0; j < 40; ++j)
                        v = fmaf(b2[k * 40 + j], w2d[(k * 40 + j) * 40 + g], v);
                v *= 0.5f;
            } else {
                v = 0.5f * (b2[g - 40] + b2[40 + g - 40]);
            }
            g_b3[g] = v;
        }
    }
}

__global__ void hist_kernel(const int* __restrict__ col) {
    int i = blockIdx.x * blockDim.x + threadIdx.x;
    if (i < EE) atomicAdd(&g_deg[col[i]], 1);
}

__global__ void scan_kernel() {
    __shared__ int part[1024];
    const int t = threadIdx.x;
    const int CH = (NN + 1023) / 1024;
    int base = t * CH;
    int hi = base + CH; if (hi > NN) hi = NN;
    int sum = 0;
    for (int i = base; i < hi; ++i) sum += g_deg[i];
    part[t] = sum;
    __syncthreads();
    for (int off = 1; off < 1024; off <<= 1) {
        int v = (t >= off) ? part[t - off] : 0;
        __syncthreads();
        part[t] += v;
        __syncthreads();
    }
    int run = part[t] - sum;
    for (int i = base; i < hi; ++i) {
        int d = g_deg[i];
        g_off[i] = run;
        g_cur[i] = run;
        g_dinv[i] = (d > 0) ? rsqrtf((float)d) : 0.0f;
        run += d;
    }
    if (t == 1023) g_off[NN] = part[1023];
}

// 2 edges per thread for MLP across ATOMG latency
__global__ void fill_kernel(const int* __restrict__ row, const int* __restrict__ col) {
    int base = (blockIdx.x * blockDim.x + threadIdx.x) * 2;
    if (base + 1 < EE) {
        int r0 = row[base], c0 = col[base];
        int r1 = row[base + 1], c1 = col[base + 1];
        float dr0 = g_dinv[r0], dc0 = g_dinv[c0];
        float dr1 = g_dinv[r1], dc1 = g_dinv[c1];
        int p0 = atomicAdd(&g_cur[c0], 1);
        int p1 = atomicAdd(&g_cur[c1], 1);
        g_srce[p0] = r0; g_ew[p0] = dr0 * dc0;
        g_srce[p1] = r1; g_ew[p1] = dr1 * dc1;
    } else if (base < EE) {
        int r0 = row[base], c0 = col[base];
        int p0 = atomicAdd(&g_cur[c0], 1);
        g_srce[p0] = r0;
        g_ew[p0]   = g_dinv[r0] * g_dinv[c0];
    }
}

// ---------------- GEMM1: C[N,128] = X[N,128] @ W[128,128], +bias on cols 64..127 ----
// 128x128 block tile, 256 threads, 8x8 micro-tile, f32x2 packed FMA.
__global__ void __launch_bounds__(256)
gemm128_kernel(const float* __restrict__ X, const float* __restrict__ W,
               const float* __restrict__ bias64, float* __restrict__ C, int nrows) {
    __shared__ float xs[16][132];   // [f][m]
    __shared__ float ws[16][128];   // [f][j]

    const int tid = threadIdx.x;
    const int tx  = tid & 15;              // 16 groups * 8 = 128 cols
    const int ty  = tid >> 4;              // 16 groups * 8 = 128 rows
    const int n0  = blockIdx.x * 128;

    u64 acc[8][4] = {};

    for (int f0 = 0; f0 < 128; f0 += 16) {
        #pragma unroll
        for (int l = 0; l < 2; ++l) {
            int idx = tid + l * 256;       // 0..511
            int m = idx >> 2, fq = idx & 3;
            float4 v = make_float4(0.f, 0.f, 0.f, 0.f);
            if (n0 + m < nrows)
                v = *(const float4*)&X[(size_t)(n0 + m) * 128 + f0 + fq * 4];
            xs[fq * 4 + 0][m] = v.x;
            xs[fq * 4 + 1][m] = v.y;
            xs[fq * 4 + 2][m] = v.z;
            xs[fq * 4 + 3][m] = v.w;
        }
        #pragma unroll
        for (int l = 0; l < 2; ++l) {
            int idx = tid + l * 256;       // 0..511 float4 slots
            int f = idx >> 5, j4 = idx & 31;
            *(float4*)&ws[f][j4 * 4] = *(const float4*)&W[(size_t)(f0 + f) * 128 + j4 * 4];
        }
        __syncthreads();
        #pragma unroll
        for (int f = 0; f < 16; ++f) {
            float4 xa = *(const float4*)&xs[f][ty * 8];
            float4 xb = *(const float4*)&xs[f][ty * 8 + 4];
            const u64* wp = (const u64*)&ws[f][tx * 8];
            u64 w0 = wp[0], w1 = wp[1], w2 = wp[2], w3 = wp[3];
            u64 xr;
            xr = pack2(xa.x, xa.x);
            ffma2(acc[0][0], xr, w0); ffma2(acc[0][1], xr, w1);
            ffma2(acc[0][2], xr, w2); ffma2(acc[0][3], xr, w3);
            xr = pack2(xa.y, xa.y);
            ffma2(acc[1][0], xr, w0); ffma2(acc[1][1], xr, w1);
            ffma2(acc[1][2], xr, w2); ffma2(acc[1][3], xr, w3);
            xr = pack2(xa.z, xa.z);
            ffma2(acc[2][0], xr, w0); ffma2(acc[2][1], xr, w1);
            ffma2(acc[2][2], xr, w2); ffma2(acc[2][3], xr, w3);
            xr = pack2(xa.w, xa.w);
            ffma2(acc[3][0], xr, w0); ffma2(acc[3][1], xr, w1);
            ffma2(acc[3][2], xr, w2); ffma2(acc[3][3], xr, w3);
            xr = pack2(xb.x, xb.x);
            ffma2(acc[4][0], xr, w0); ffma2(acc[4][1], xr, w1);
            ffma2(acc[4][2], xr, w2); ffma2(acc[4][3], xr, w3);
            xr = pack2(xb.y, xb.y);
            ffma2(acc[5][0], xr, w0); ffma2(acc[5][1], xr, w1);
            ffma2(acc[5][2], xr, w2); ffma2(acc[5][3], xr, w3);
            xr = pack2(xb.z, xb.z);
            ffma2(acc[6][0], xr, w0); ffma2(acc[6][1], xr, w1);
            ffma2(acc[6][2], xr, w2); ffma2(acc[6][3], xr, w3);
            xr = pack2(xb.w, xb.w);
            ffma2(acc[7][0], xr, w0); ffma2(acc[7][1], xr, w1);
            ffma2(acc[7][2], xr, w2); ffma2(acc[7][3], xr, w3);
        }
        __syncthreads();
    }

    const int jb = tx * 8;
    float bv[8];
    #pragma unroll
    for (int c = 0; c < 8; ++c) {
        int j = jb + c;
        bv[c] = (j >= 64) ? bias64[j - 64] : 0.0f;
    }
    #pragma unroll
    for (int r = 0; r < 8; ++r) {
        int n = n0 + ty * 8 + r;
        if (n >= nrows) continue;
        float2 p0 = unpack2(acc[r][0]);
        float2 p1 = unpack2(acc[r][1]);
        float2 p2 = unpack2(acc[r][2]);
        float2 p3 = unpack2(acc[r][3]);
        *(float4*)&C[(size_t)n * 128 + jb] =
            make_float4(p0.x + bv[0], p0.y + bv[1], p1.x + bv[2], p1.y + bv[3]);
        *(float4*)&C[(size_t)n * 128 + jb + 4] =
            make_float4(p2.x + bv[4], p2.y + bv[5], p3.x + bv[6], p3.y + bv[7]);
    }
}

// ---------------- small GEMM body: 128x32 tile, f32x2, optional bias ----------------
__device__ __forceinline__ void gemm32_body(
        const float* __restrict__ X, int ldx,
        const float* __restrict__ W, int ldw,
        const float* __restrict__ bias,
        float* __restrict__ C, int ldc,
        int nrows, int F, int J, int n0, int j0) {
    __shared__ float xs[16][132];
    __shared__ float ws[16][32];

    const int tid = threadIdx.x;
    const int tx  = tid & 7;               // 8 * 4 = 32 cols
    const int ty  = tid >> 3;              // 32 * 4 = 128 rows

    u64 acc[4][2] = {};

    for (int f0 = 0; f0 < F; f0 += 16) {
        #pragma unroll
        for (int l = 0; l < 2; ++l) {
            int idx = tid + l * 256;
            int m = idx >> 2, fq = idx & 3;
            float4 v = make_float4(0.f, 0.f, 0.f, 0.f);
            if (n0 + m < nrows)
                v = *(const float4*)&X[(size_t)(n0 + m) * ldx + f0 + fq * 4];
            xs[fq * 4 + 0][m] = v.x;
            xs[fq * 4 + 1][m] = v.y;
            xs[fq * 4 + 2][m] = v.z;
            xs[fq * 4 + 3][m] = v.w;
        }
        #pragma unroll
        for (int l = 0; l < 2; ++l) {
            int idx = tid + l * 256;       // 0..511
            int f = idx >> 5, j = idx & 31;
            ws[f][j] = (j0 + j < J) ? W[(size_t)(f0 + f) * ldw + j0 + j] : 0.0f;
        }
        __syncthreads();
        #pragma unroll
        for (int f = 0; f < 16; ++f) {
            const u64* wp = (const u64*)&ws[f][tx * 4];
            u64 w0 = wp[0], w1 = wp[1];
            float4 xa = *(const float4*)&xs[f][ty * 4];
            u64 xr;
            xr = pack2(xa.x, xa.x); ffma2(acc[0][0], xr, w0); ffma2(acc[0][1], xr, w1);
            xr = pack2(xa.y, xa.y); ffma2(acc[1][0], xr, w0); ffma2(acc[1][1], xr, w1);
            xr = pack2(xa.z, xa.z); ffma2(acc[2][0], xr, w0); ffma2(acc[2][1], xr, w1);
            xr = pack2(xa.w, xa.w); ffma2(acc[3][0], xr, w0); ffma2(acc[3][1], xr, w1);
        }
        __syncthreads();
    }

    const int jb = j0 + tx * 4;
    float bv[4] = {0.f, 0.f, 0.f, 0.f};
    if (bias) {
        #pragma unroll
        for (int c = 0; c < 4; ++c)
            if (jb + c < J) bv[c] = bias[jb + c];
    }
    #pragma unroll
    for (int r = 0; r < 4; ++r) {
        int n = n0 + ty * 4 + r;
        if (n >= nrows) continue;
        float2 p0 = unpack2(acc[r][0]);
        float2 p1 = unpack2(acc[r][1]);
        float v[4] = {p0.x + bv[0], p0.y + bv[1], p1.x + bv[2], p1.y + bv[3]};
        if (jb + 3 < J) {
            *(float4*)&C[(size_t)n * ldc + jb] = make_float4(v[0], v[1], v[2], v[3]);
        } else {
            #pragma unroll
            for (int c = 0; c < 4; ++c)
                if (jb + c < J) C[(size_t)n * ldc + jb + c] = v[c];
        }
    }
}

__global__ void __launch_bounds__(256)
gemm32_kernel(const float* __restrict__ X, int ldx,
              const float* __restrict__ W, int ldw,
              const float* __restrict__ bias,
              float* __restrict__ C, int ldc,
              int nrows, int F, int J) {
    gemm32_body(X, ldx, W, ldw, bias, C, ldc, nrows, F, J,
                blockIdx.x * 128, blockIdx.y * 32);
}

// block-diagonal deep matmul: stack s = blockIdx.y, two 32x32 GEMMs in one grid
__global__ void __launch_bounds__(256)
gemm_diag_kernel(const float* __restrict__ B, const float* __restrict__ w1d,
                 float* __restrict__ C, int nrows) {
    int s = blockIdx.y;
    gemm32_body(B + 32 * s, 64, w1d + 1024 * s, 32, nullptr,
                C + 32 * s, 64, nrows, 32, 32, blockIdx.x * 128, 0);
}

// ---------------- width-64 propagate (conv1): gather + root' (+relu / +mean) ----
// root' already includes bias (folded in gemm128 epilogue)
template <bool FINAL>
__global__ void prop64_kernel(const float* __restrict__ src, int lds,
                              const float* __restrict__ root, int ldr,
                              float* __restrict__ out, int ldo) {
    const int gwarp = (blockIdx.x * blockDim.x + threadIdx.x) >> 5;
    const int lane  = threadIdx.x & 31;
    if (gwarp >= NN) return;
    const int n   = gwarp;
    const int beg = g_off[n];
    const int end = g_off[n + 1];

    float a0 = 0.f, a1 = 0.f;
    int e = beg;
    for (; e + 4 <= end; e += 4) {
        int   s0 = g_srce[e],     s1 = g_srce[e + 1];
        int   s2 = g_srce[e + 2], s3 = g_srce[e + 3];
        float w0 = g_ew[e],       w1 = g_ew[e + 1];
        float w2 = g_ew[e + 2],   w3 = g_ew[e + 3];
        const float* p0 = src + (size_t)s0 * lds;
        const float* p1 = src + (size_t)s1 * lds;
        const float* p2 = src + (size_t)s2 * lds;
        const float* p3 = src + (size_t)s3 * lds;
        float u0 = p0[lane],      u1 = p1[lane],      u2 = p2[lane],      u3 = p3[lane];
        float v0 = p0[lane + 32], v1 = p1[lane + 32], v2 = p2[lane + 32], v3 = p3[lane + 32];
        a0 = fmaf(w0, u0, a0); a0 = fmaf(w1, u1, a0);
        a0 = fmaf(w2, u2, a0); a0 = fmaf(w3, u3, a0);
        a1 = fmaf(w0, v0, a1); a1 = fmaf(w1, v1, a1);
        a1 = fmaf(w2, v2, a1); a1 = fmaf(w3, v3, a1);
    }
    for (; e < end; ++e) {
        int   s0 = g_srce[e];
        float w0 = g_ew[e];
        const float* p0 = src + (size_t)s0 * lds;
        a0 = fmaf(w0, p0[lane], a0);
        a1 = fmaf(w0, p0[lane + 32], a1);
    }

    const float* rp = root + (size_t)n * ldr;
    float y0 = fmaxf(a0 + rp[lane],      0.f);
    float y1 = fmaxf(a1 + rp[lane + 32], 0.f);

    if (!FINAL) {
        float* op = out + (size_t)n * ldo;
        op[lane] = y0;
        op[lane + 32] = y1;
    } else {
        out[(size_t)n * ldo + lane] = 0.5f * (y0 + y1);
    }
}

// ---------------- width-32 pure gather: PH = A(H) ----------------
__global__ void prop32_kernel(const float* __restrict__ src, int lds,
                              float* __restrict__ out, int ldo) {
    const int gwarp = (blockIdx.x * blockDim.x + threadIdx.x) >> 5;
    const int lane  = threadIdx.x & 31;
    if (gwarp >= NN) return;
    const int n   = gwarp;
    const int beg = g_off[n];
    const int end = g_off[n + 1];

    float a0 = 0.f;
    int e = beg;
    for (; e + 4 <= end; e += 4) {
        int   s0 = g_srce[e],     s1 = g_srce[e + 1];
        int   s2 = g_srce[e + 2], s3 = g_srce[e + 3];
        float w0 = g_ew[e],       w1 = g_ew[e + 1];
        float w2 = g_ew[e + 2],   w3 = g_ew[e + 3];
        float u0 = src[(size_t)s0 * lds + lane];
        float u1 = src[(size_t)s1 * lds + lane];
        float u2 = src[(size_t)s2 * lds + lane];
        float u3 = src[(size_t)s3 * lds + lane];
        a0 = fmaf(w0, u0, a0); a0 = fmaf(w1, u1, a0);
        a0 = fmaf(w2, u2, a0); a0 = fmaf(w3, u3, a0);
    }
    for (; e < end; ++e)
        a0 = fmaf(g_ew[e], src[(size_t)g_srce[e] * lds + lane], a0);
    out[(size_t)n * ldo + lane] = a0;
}

// ---------------- width-40 final propagate + log_softmax ----------------
__global__ void prop40_kernel(const float* __restrict__ src, int lds,
                              const float* __restrict__ root, int ldr,
                              float* __restrict__ out) {
    const int gwarp = (blockIdx.x * blockDim.x + threadIdx.x) >> 5;
    const int lane  = threadIdx.x & 31;
    if (gwarp >= NN) return;
    const int n   = gwarp;
    const int beg = g_off[n];
    const int end = g_off[n + 1];

    float a0 = 0.f, a1 = 0.f;
    int e = beg;
    for (; e + 4 <= end; e += 4) {
        int   s0 = g_srce[e],     s1 = g_srce[e + 1];
        int   s2 = g_srce[e + 2], s3 = g_srce[e + 3];
        float w0 = g_ew[e],       w1 = g_ew[e + 1];
        float w2 = g_ew[e + 2],   w3 = g_ew[e + 3];
        const float* p0 = src + (size_t)s0 * lds;
        const float* p1 = src + (size_t)s1 * lds;
        const float* p2 = src + (size_t)s2 * lds;
        const float* p3 = src + (size_t)s3 * lds;
        a0 = fmaf(w0, p0[lane], a0); a0 = fmaf(w1, p1[lane], a0);
        a0 = fmaf(w2, p2[lane], a0); a0 = fmaf(w3, p3[lane], a0);
        if (lane < 8) {
            a1 = fmaf(w0, p0[lane + 32], a1); a1 = fmaf(w1, p1[lane + 32], a1);
            a1 = fmaf(w2, p2[lane + 32], a1); a1 = fmaf(w3, p3[lane + 32], a1);
        }
    }
    for (; e < end; ++e) {
        float w0 = g_ew[e];
        const float* p0 = src + (size_t)g_srce[e] * lds;
        a0 = fmaf(w0, p0[lane], a0);
        if (lane < 8) a1 = fmaf(w0, p0[lane + 32], a1);
    }

    const float* rp = root + (size_t)n * ldr;
    float m0 = a0 + rp[lane];
    float m1 = (lane < 8) ? (a1 + rp[lane + 32]) : -3.0e38f;

    float mv = fmaxf(m0, m1);
    #pragma unroll
    for (int o = 16; o; o >>= 1) mv = fmaxf(mv, __shfl_xor_sync(0xffffffffu, mv, o));
    float s = expf(m0 - mv) + ((lane < 8) ? expf(m1 - mv) : 0.0f);
    #pragma unroll
    for (int o = 16; o; o >>= 1) s += __shfl_xor_sync(0xffffffffu, s, o);
    float l = mv + logf(s);
    out[(size_t)n * 40 + lane] = m0 - l;
    if (lane < 8) out[(size_t)n * 40 + 32 + lane] = m1 - l;
}

// ---------------- launch ----------------
extern "C" void kernel_launch(void* const* d_in, const int* in_sizes, int n_in,
                              void* d_out, int out_size) {
    const float* x    = (const float*)d_in[0];
    const int*   eidx = (const int*)  d_in[1];
    const float* w1i  = (const float*)d_in[2];
    const float* w1d  = (const float*)d_in[3];
    const float* w1r  = (const float*)d_in[4];
    const float* b1   = (const float*)d_in[5];
    const float* w2i  = (const float*)d_in[6];
    const float* w2d  = (const float*)d_in[7];
    const float* w2r  = (const float*)d_in[8];
    const float* b2   = (const float*)d_in[9];
    float* outp = (float*)d_out;

    const int* row = eidx;
    const int* col = eidx + EE;

    float *A, *B, *C, *HH, *D, *Wp1, *W3, *b3;
    cudaGetSymbolAddress((void**)&A,   g_A);
    cudaGetSymbolAddress((void**)&B,   g_B);
    cudaGetSymbolAddress((void**)&C,   g_C);
    cudaGetSymbolAddress((void**)&HH,  g_HH);
    cudaGetSymbolAddress((void**)&D,   g_D);
    cudaGetSymbolAddress((void**)&Wp1, g_Wp1);
    cudaGetSymbolAddress((void**)&W3,  g_W3);
    cudaGetSymbolAddress((void**)&b3,  g_b3);

    const int TB = 256;
    const int nblkE  = (EE + TB - 1) / TB;             // 3125
    const int nblkE2 = (EE / 2 + TB - 1) / TB;         // 1563
    const int nblkW  = (NN * 32 + TB - 1) / TB;        // 6250 (warp per node)
    const int gR = (NN + 127) / 128;                   // 391 row tiles

    // graph prep + weight packing / folding
    init_kernel<<<(NN + TB - 1) / TB, TB>>>(w1i, w1r, w2i, w2d, w2r, b2);
    hist_kernel<<<nblkE, TB>>>(col);
    scan_kernel<<<1, 1024>>>();
    fill_kernel<<<nblkE2, TB>>>(row, col);

    // ---- conv1 ----
    gemm128_kernel<<<gR, TB>>>(x, Wp1, b1, A, NN);               // bias folded into root cols
    prop64_kernel<false><<<nblkW, TB>>>(A, 128, A + 64, 128, B, 64);
    gemm_diag_kernel<<<dim3(gR, 2), TB>>>(B, w1d, C, NN);
    prop64_kernel<true><<<nblkW, TB>>>(C, 64, A + 64, 128, HH + 32, 64);  // H -> cols 32..63

    // ---- conv2 (algebraically folded) ----
    prop32_kernel<<<nblkW, TB>>>(HH + 32, 64, HH, 64);           // PH -> cols 0..31
    gemm32_kernel<<<dim3(gR, 3), TB>>>(HH, 64, W3, 80, b3, D, 80, NN, 64, 80);
    prop40_kernel<<<nblkW, TB>>>(D, 80, D + 40, 80, outp);
}

// round 5
// speedup vs baseline: 1.1858x; 1.0091x over previous
#include <cuda_runtime.h>
#include <math.h>

#define NN 50000
#define EE 800000

typedef unsigned long long u64;

// ---------------- f32x2 packed-FMA helpers (bit-identical fp32) ----------------
__device__ __forceinline__ u64 pack2(float lo, float hi) {
    u64 r; asm("mov.b64 %0, {%1, %2};" : "=l"(r) : "f"(lo), "f"(hi)); return r;
}
__device__ __forceinline__ void ffma2(u64& d, u64 a, u64 b) {
    asm("fma.rn.f32x2 %0, %1, %2, %0;" : "+l"(d) : "l"(a), "l"(b));
}
__device__ __forceinline__ float2 unpack2(u64 v) {
    float2 f; asm("mov.b64 {%0, %1}, %2;" : "=f"(f.x), "=f"(f.y) : "l"(v)); return f;
}

// ---------------- scratch (device globals, no runtime alloc) ----------------
__device__ int   g_deg[NN];
__device__ int   g_off[NN + 1];
__device__ int   g_cur[NN];
__device__ float g_dinv[NN];
__device__ int2  g_edge[EE];              // {src, __float_as_int(ew)}

__device__ float g_A [(size_t)NN * 128];  // conv1: [init(64) | root+b1(64)]
__device__ float g_B [(size_t)NN * 64];   // conv1 after t=0
__device__ float g_C [(size_t)NN * 64];   // conv1 deep matmul out
__device__ float g_HH[(size_t)NN * 64];   // [PH(32) | H(32)]
__device__ float g_D [(size_t)NN * 80];   // [G(40) | Rm+bm(40)]

__device__ float g_Wp1[128 * 128];        // packed [w1_init | w1_root]
__device__ float g_W3 [64 * 80];          // folded conv2 weights
__device__ float g_b3 [80];               // folded conv2 bias

// ---------------- initD: zero degree ----------------
__global__ void initD_kernel() {
    int i = blockIdx.x * blockDim.x + threadIdx.x;
    if (i < NN) g_deg[i] = 0;
}

// ---------------- initW: pack Wp1 + fold conv2 weights ----------------
__global__ void initW_kernel(const float* __restrict__ w1i, const float* __restrict__ w1r,
                             const float* __restrict__ w2i, const float* __restrict__ w2d,
                             const float* __restrict__ w2r, const float* __restrict__ b2) {
    int i = blockIdx.x * blockDim.x + threadIdx.x;
    if (i < 16384) {                       // Wp1 : 128 x 128 = [w1_init | w1_root]
        int f = i >> 7, j = i & 127;
        float v;
        if (j < 64) { int k = j >> 5, h = j & 31; v = w1i[(k * 128 + f) * 32 + h]; }
        else        { int j2 = j - 64; int k = j2 >> 5, h = j2 & 31; v = w1r[(k * 128 + f) * 32 + h]; }
        g_Wp1[i] = v;
    } else if (i < 16384 + 64 * 80 + 80) {
        int i2 = i - 16384;
        if (i2 < 64 * 80) {
            int f = i2 / 80, g = i2 % 80;
            float v = 0.0f;
            if (g < 40) {
                const float* wa = (f < 32) ? w2i : w2r;
                int fr = (f < 32) ? f : f - 32;
                #pragma unroll
                for (int k = 0; k < 2; ++k) {
                    float s = 0.0f;
                    for (int j = 0; j < 40; ++j)
                        s = fmaf(wa[(k * 32 + fr) * 40 + j], w2d[(k * 40 + j) * 40 + g], s);
                    v += s;
                }
                v *= 0.5f;
            } else if (f >= 32) {
                int fr = f - 32, gg = g - 40;
                v = 0.5f * (w2r[(0 * 32 + fr) * 40 + gg] + w2r[(1 * 32 + fr) * 40 + gg]);
            }
            g_W3[i2] = v;
        } else {
            int g = i2 - 64 * 80;
            float v;
            if (g < 40) {
                v = 0.0f;
                #pragma unroll
                for (int k = 0; k < 2; ++k)
                    for (int j = 0; j < 40; ++j)
                        v = fmaf(b2[k * 40 + j], w2d[(k * 40 + j) * 40 + g], v);
                v *= 0.5f;
            } else {
                v = 0.5f * (b2[g - 40] + b2[40 + g - 40]);
            }
            g_b3[g] = v;
        }
    }
}

__global__ void hist_kernel(const int* __restrict__ col) {
    int i = (blockIdx.x * blockDim.x + threadIdx.x) * 2;
    if (i + 1 < EE) {
        int2 c = *(const int2*)&col[i];
        atomicAdd(&g_deg[c.x], 1);
        atomicAdd(&g_deg[c.y], 1);
    } else if (i < EE) {
        atomicAdd(&g_deg[col[i]], 1);
    }
}

__global__ void scan_kernel() {
    __shared__ int part[1024];
    const int t = threadIdx.x;
    const int CH = (NN + 1023) / 1024;
    int base = t * CH;
    int hi = base + CH; if (hi > NN) hi = NN;
    int sum = 0;
    for (int i = base; i < hi; ++i) sum += g_deg[i];
    part[t] = sum;
    __syncthreads();
    for (int off = 1; off < 1024; off <<= 1) {
        int v = (t >= off) ? part[t - off] : 0;
        __syncthreads();
        part[t] += v;
        __syncthreads();
    }
    int run = part[t] - sum;
    for (int i = base; i < hi; ++i) {
        int d = g_deg[i];
        g_off[i] = run;
        g_cur[i] = run;
        g_dinv[i] = (d > 0) ? rsqrtf((float)d) : 0.0f;
        run += d;
    }
    if (t == 1023) g_off[NN] = part[1023];
}

__global__ void fill_kernel(const int* __restrict__ row, const int* __restrict__ col) {
    int base = (blockIdx.x * blockDim.x + threadIdx.x) * 2;
    if (base + 1 < EE) {
        int2 r = *(const int2*)&row[base];
        int2 c = *(const int2*)&col[base];
        float dr0 = g_dinv[r.x], dc0 = g_dinv[c.x];
        float dr1 = g_dinv[r.y], dc1 = g_dinv[c.y];
        int p0 = atomicAdd(&g_cur[c.x], 1);
        int p1 = atomicAdd(&g_cur[c.y], 1);
        g_edge[p0] = make_int2(r.x, __float_as_int(dr0 * dc0));
        g_edge[p1] = make_int2(r.y, __float_as_int(dr1 * dc1));
    } else if (base < EE) {
        int r0 = row[base], c0 = col[base];
        int p0 = atomicAdd(&g_cur[c0], 1);
        g_edge[p0] = make_int2(r0, __float_as_int(g_dinv[r0] * g_dinv[c0]));
    }
}

// ---------------- GEMM1: C[N,128] = X[N,128] @ W[128,128], +bias on cols 64..127 ----
__global__ void __launch_bounds__(256)
gemm128_kernel(const float* __restrict__ X, const float* __restrict__ W,
               const float* __restrict__ bias64, float* __restrict__ C, int nrows) {
    __shared__ float xs[16][132];
    __shared__ float ws[16][128];

    const int tid = threadIdx.x;
    const int tx  = tid & 15;
    const int ty  = tid >> 4;
    const int n0  = blockIdx.x * 128;

    u64 acc[8][4] = {};

    for (int f0 = 0; f0 < 128; f0 += 16) {
        #pragma unroll
        for (int l = 0; l < 2; ++l) {
            int idx = tid + l * 256;
            int m = idx >> 2, fq = idx & 3;
            float4 v = make_float4(0.f, 0.f, 0.f, 0.f);
            if (n0 + m < nrows)
                v = *(const float4*)&X[(size_t)(n0 + m) * 128 + f0 + fq * 4];
            xs[fq * 4 + 0][m] = v.x;
            xs[fq * 4 + 1][m] = v.y;
            xs[fq * 4 + 2][m] = v.z;
            xs[fq * 4 + 3][m] = v.w;
        }
        #pragma unroll
        for (int l = 0; l < 2; ++l) {
            int idx = tid + l * 256;
            int f = idx >> 5, j4 = idx & 31;
            *(float4*)&ws[f][j4 * 4] = *(const float4*)&W[(size_t)(f0 + f) * 128 + j4 * 4];
        }
        __syncthreads();
        #pragma unroll
        for (int f = 0; f < 16; ++f) {
            float4 xa = *(const float4*)&xs[f][ty * 8];
            float4 xb = *(const float4*)&xs[f][ty * 8 + 4];
            const u64* wp = (const u64*)&ws[f][tx * 8];
            u64 w0 = wp[0], w1 = wp[1], w2 = wp[2], w3 = wp[3];
            u64 xr;
            xr = pack2(xa.x, xa.x);
            ffma2(acc[0][0], xr, w0); ffma2(acc[0][1], xr, w1);
            ffma2(acc[0][2], xr, w2); ffma2(acc[0][3], xr, w3);
            xr = pack2(xa.y, xa.y);
            ffma2(acc[1][0], xr, w0); ffma2(acc[1][1], xr, w1);
            ffma2(acc[1][2], xr, w2); ffma2(acc[1][3], xr, w3);
            xr = pack2(xa.z, xa.z);
            ffma2(acc[2][0], xr, w0); ffma2(acc[2][1], xr, w1);
            ffma2(acc[2][2], xr, w2); ffma2(acc[2][3], xr, w3);
            xr = pack2(xa.w, xa.w);
            ffma2(acc[3][0], xr, w0); ffma2(acc[3][1], xr, w1);
            ffma2(acc[3][2], xr, w2); ffma2(acc[3][3], xr, w3);
            xr = pack2(xb.x, xb.x);
            ffma2(acc[4][0], xr, w0); ffma2(acc[4][1], xr, w1);
            ffma2(acc[4][2], xr, w2); ffma2(acc[4][3], xr, w3);
            xr = pack2(xb.y, xb.y);
            ffma2(acc[5][0], xr, w0); ffma2(acc[5][1], xr, w1);
            ffma2(acc[5][2], xr, w2); ffma2(acc[5][3], xr, w3);
            xr = pack2(xb.z, xb.z);
            ffma2(acc[6][0], xr, w0); ffma2(acc[6][1], xr, w1);
            ffma2(acc[6][2], xr, w2); ffma2(acc[6][3], xr, w3);
            xr = pack2(xb.w, xb.w);
            ffma2(acc[7][0], xr, w0); ffma2(acc[7][1], xr, w1);
            ffma2(acc[7][2], xr, w2); ffma2(acc[7][3], xr, w3);
        }
        __syncthreads();
    }

    const int jb = tx * 8;
    float bv[8];
    #pragma unroll
    for (int c = 0; c < 8; ++c) {
        int j = jb + c;
        bv[c] = (j >= 64) ? bias64[j - 64] : 0.0f;
    }
    #pragma unroll
    for (int r = 0; r < 8; ++r) {
        int n = n0 + ty * 8 + r;
        if (n >= nrows) continue;
        float2 p0 = unpack2(acc[r][0]);
        float2 p1 = unpack2(acc[r][1]);
        float2 p2 = unpack2(acc[r][2]);
        float2 p3 = unpack2(acc[r][3]);
        *(float4*)&C[(size_t)n * 128 + jb] =
            make_float4(p0.x + bv[0], p0.y + bv[1], p1.x + bv[2], p1.y + bv[3]);
        *(float4*)&C[(size_t)n * 128 + jb + 4] =
            make_float4(p2.x + bv[4], p2.y + bv[5], p3.x + bv[6], p3.y + bv[7]);
    }
}

// ---------------- small GEMM body: 128x32 tile, f32x2, optional bias ----------------
__device__ __forceinline__ void gemm32_body(
        const float* __restrict__ X, int ldx,
        const float* __restrict__ W, int ldw,
        const float* __restrict__ bias,
        float* __restrict__ C, int ldc,
        int nrows, int F, int J, int n0, int j0) {
    __shared__ float xs[16][132];
    __shared__ float ws[16][32];

    const int tid = threadIdx.x;
    const int tx  = tid & 7;
    const int ty  = tid >> 3;

    u64 acc[4][2] = {};

    for (int f0 = 0; f0 < F; f0 += 16) {
        #pragma unroll
        for (int l = 0; l < 2; ++l) {
            int idx = tid + l * 256;
            int m = idx >> 2, fq = idx & 3;
            float4 v = make_float4(0.f, 0.f, 0.f, 0.f);
            if (n0 + m < nrows)
                v = *(const float4*)&X[(size_t)(n0 + m) * ldx + f0 + fq * 4];
            xs[fq * 4 + 0][m] = v.x;
            xs[fq * 4 + 1][m] = v.y;
            xs[fq * 4 + 2][m] = v.z;
            xs[fq * 4 + 3][m] = v.w;
        }
        #pragma unroll
        for (int l = 0; l < 2; ++l) {
            int idx = tid + l * 256;
            int f = idx >> 5, j = idx & 31;
            ws[f][j] = (j0 + j < J) ? W[(size_t)(f0 + f) * ldw + j0 + j] : 0.0f;
        }
        __syncthreads();
        #pragma unroll
        for (int f = 0; f < 16; ++f) {
            const u64* wp = (const u64*)&ws[f][tx * 4];
            u64 w0 = wp[0], w1 = wp[1];
            float4 xa = *(const float4*)&xs[f][ty * 4];
            u64 xr;
            xr = pack2(xa.x, xa.x); ffma2(acc[0][0], xr, w0); ffma2(acc[0][1], xr, w1);
            xr = pack2(xa.y, xa.y); ffma2(acc[1][0], xr, w0); ffma2(acc[1][1], xr, w1);
            xr = pack2(xa.z, xa.z); ffma2(acc[2][0], xr, w0); ffma2(acc[2][1], xr, w1);
            xr = pack2(xa.w, xa.w); ffma2(acc[3][0], xr, w0); ffma2(acc[3][1], xr, w1);
        }
        __syncthreads();
    }

    const int jb = j0 + tx * 4;
    float bv[4] = {0.f, 0.f, 0.f, 0.f};
    if (bias) {
        #pragma unroll
        for (int c = 0; c < 4; ++c)
            if (jb + c < J) bv[c] = bias[jb + c];
    }
    #pragma unroll
    for (int r = 0; r < 4; ++r) {
        int n = n0 + ty * 4 + r;
        if (n >= nrows) continue;
        float2 p0 = unpack2(acc[r][0]);
        float2 p1 = unpack2(acc[r][1]);
        float v[4] = {p0.x + bv[0], p0.y + bv[1], p1.x + bv[2], p1.y + bv[3]};
        if (jb + 3 < J) {
            *(float4*)&C[(size_t)n * ldc + jb] = make_float4(v[0], v[1], v[2], v[3]);
        } else {
            #pragma unroll
            for (int c = 0; c < 4; ++c)
                if (jb + c < J) C[(size_t)n * ldc + jb + c] = v[c];
        }
    }
}

__global__ void __launch_bounds__(256)
gemm32_kernel(const float* __restrict__ X, int ldx,
              const float* __restrict__ W, int ldw,
              const float* __restrict__ bias,
              float* __restrict__ C, int ldc,
              int nrows, int F, int J) {
    gemm32_body(X, ldx, W, ldw, bias, C, ldc, nrows, F, J,
                blockIdx.x * 128, blockIdx.y * 32);
}

__global__ void __launch_bounds__(256)
gemm_diag_kernel(const float* __restrict__ B, const float* __restrict__ w1d,
                 float* __restrict__ C, int nrows) {
    int s = blockIdx.y;
    gemm32_body(B + 32 * s, 64, w1d + 1024 * s, 32, nullptr,
                C + 32 * s, 64, nrows, 32, 32, blockIdx.x * 128, 0);
}

// ---------------- width-64 propagate (conv1): gather + root' (+relu / +mean) ----
template <bool FINAL>
__global__ void prop64_kernel(const float* __restrict__ src, int lds,
                              const float* __restrict__ root, int ldr,
                              float* __restrict__ out, int ldo) {
    const int gwarp = (blockIdx.x * blockDim.x + threadIdx.x) >> 5;
    const int lane  = threadIdx.x & 31;
    if (gwarp >= NN) return;
    const int n   = gwarp;
    const int beg = g_off[n];
    const int end = g_off[n + 1];

    float a0 = 0.f, a1 = 0.f;
    int e = beg;
    for (; e + 4 <= end; e += 4) {
        int2 e0 = g_edge[e],     e1 = g_edge[e + 1];
        int2 e2 = g_edge[e + 2], e3 = g_edge[e + 3];
        float w0 = __int_as_float(e0.y), w1 = __int_as_float(e1.y);
        float w2 = __int_as_float(e2.y), w3 = __int_as_float(e3.y);
        const float* p0 = src + (size_t)e0.x * lds;
        const float* p1 = src + (size_t)e1.x * lds;
        const float* p2 = src + (size_t)e2.x * lds;
        const float* p3 = src + (size_t)e3.x * lds;
        float u0 = p0[lane],      u1 = p1[lane],      u2 = p2[lane],      u3 = p3[lane];
        float v0 = p0[lane + 32], v1 = p1[lane + 32], v2 = p2[lane + 32], v3 = p3[lane + 32];
        a0 = fmaf(w0, u0, a0); a0 = fmaf(w1, u1, a0);
        a0 = fmaf(w2, u2, a0); a0 = fmaf(w3, u3, a0);
        a1 = fmaf(w0, v0, a1); a1 = fmaf(w1, v1, a1);
        a1 = fmaf(w2, v2, a1); a1 = fmaf(w3, v3, a1);
    }
    for (; e < end; ++e) {
        int2 e0 = g_edge[e];
        float w0 = __int_as_float(e0.y);
        const float* p0 = src + (size_t)e0.x * lds;
        a0 = fmaf(w0, p0[lane], a0);
        a1 = fmaf(w0, p0[lane + 32], a1);
    }

    const float* rp = root + (size_t)n * ldr;
    float y0 = fmaxf(a0 + rp[lane],      0.f);
    float y1 = fmaxf(a1 + rp[lane + 32], 0.f);

    if (!FINAL) {
        float* op = out + (size_t)n * ldo;
        op[lane] = y0;
        op[lane + 32] = y1;
    } else {
        out[(size_t)n * ldo + lane] = 0.5f * (y0 + y1);
    }
}

// ---------------- width-32 pure gather: PH = A(H) ----------------
__global__ void prop32_kernel(const float* __restrict__ src, int lds,
                              float* __restrict__ out, int ldo) {
    const int gwarp = (blockIdx.x * blockDim.x + threadIdx.x) >> 5;
    const int lane  = threadIdx.x & 31;
    if (gwarp >= NN) return;
    const int n   = gwarp;
    const int beg = g_off[n];
    const int end = g_off[n + 1];

    float a0 = 0.f;
    int e = beg;
    for (; e + 4 <= end; e += 4) {
        int2 e0 = g_edge[e],     e1 = g_edge[e + 1];
        int2 e2 = g_edge[e + 2], e3 = g_edge[e + 3];
        float w0 = __int_as_float(e0.y), w1 = __int_as_float(e1.y);
        float w2 = __int_as_float(e2.y), w3 = __int_as_float(e3.y);
        float u0 = src[(size_t)e0.x * lds + lane];
        float u1 = src[(size_t)e1.x * lds + lane];
        float u2 = src[(size_t)e2.x * lds + lane];
        float u3 = src[(size_t)e3.x * lds + lane];
        a0 = fmaf(w0, u0, a0); a0 = fmaf(w1, u1, a0);
        a0 = fmaf(w2, u2, a0); a0 = fmaf(w3, u3, a0);
    }
    for (; e < end; ++e) {
        int2 e0 = g_edge[e];
        a0 = fmaf(__int_as_float(e0.y), src[(size_t)e0.x * lds + lane], a0);
    }
    out[(size_t)n * ldo + lane] = a0;
}

// ---------------- width-40 final propagate + log_softmax ----------------
__global__ void prop40_kernel(const float* __restrict__ src, int lds,
                              const float* __restrict__ root, int ldr,
                              float* __restrict__ out) {
    const int gwarp = (blockIdx.x * blockDim.x + threadIdx.x) >> 5;
    const int lane  = threadIdx.x & 31;
    if (gwarp >= NN) return;
    const int n   = gwarp;
    const int beg = g_off[n];
    const int end = g_off[n + 1];

    float a0 = 0.f, a1 = 0.f;
    int e = beg;
    for (; e + 4 <= end; e += 4) {
        int2 e0 = g_edge[e],     e1 = g_edge[e + 1];
        int2 e2 = g_edge[e + 2], e3 = g_edge[e + 3];
        float w0 = __int_as_float(e0.y), w1 = __int_as_float(e1.y);
        float w2 = __int_as_float(e2.y), w3 = __int_as_float(e3.y);
        const float* p0 = src + (size_t)e0.x * lds;
        const float* p1 = src + (size_t)e1.x * lds;
        const float* p2 = src + (size_t)e2.x * lds;
        const float* p3 = src + (size_t)e3.x * lds;
        a0 = fmaf(w0, p0[lane], a0); a0 = fmaf(w1, p1[lane], a0);
        a0 = fmaf(w2, p2[lane], a0); a0 = fmaf(w3, p3[lane], a0);
        if (lane < 8) {
            a1 = fmaf(w0, p0[lane + 32], a1); a1 = fmaf(w1, p1[lane + 32], a1);
            a1 = fmaf(w2, p2[lane + 32], a1); a1 = fmaf(w3, p3[lane + 32], a1);
        }
    }
    for (; e < end; ++e) {
        int2 e0 = g_edge[e];
        float w0 = __int_as_float(e0.y);
        const float* p0 = src + (size_t)e0.x * lds;
        a0 = fmaf(w0, p0[lane], a0);
        if (lane < 8) a1 = fmaf(w0, p0[lane + 32], a1);
    }

    const float* rp = root + (size_t)n * ldr;
    float m0 = a0 + rp[lane];
    float m1 = (lane < 8) ? (a1 + rp[lane + 32]) : -3.0e38f;

    float mv = fmaxf(m0, m1);
    #pragma unroll
    for (int o = 16; o; o >>= 1) mv = fmaxf(mv, __shfl_xor_sync(0xffffffffu, mv, o));
    float s = expf(m0 - mv) + ((lane < 8) ? expf(m1 - mv) : 0.0f);
    #pragma unroll
    for (int o = 16; o; o >>= 1) s += __shfl_xor_sync(0xffffffffu, s, o);
    float l = mv + logf(s);
    out[(size_t)n * 40 + lane] = m0 - l;
    if (lane < 8) out[(size_t)n * 40 + 32 + lane] = m1 - l;
}

// ---------------- launch ----------------
extern "C" void kernel_launch(void* const* d_in, const int* in_sizes, int n_in,
                              void* d_out, int out_size) {
    const float* x    = (const float*)d_in[0];
    const int*   eidx = (const int*)  d_in[1];
    const float* w1i  = (const float*)d_in[2];
    const float* w1d  = (const float*)d_in[3];
    const float* w1r  = (const float*)d_in[4];
    const float* b1   = (const float*)d_in[5];
    const float* w2i  = (const float*)d_in[6];
    const float* w2d  = (const float*)d_in[7];
    const float* w2r  = (const float*)d_in[8];
    const float* b2   = (const float*)d_in[9];
    float* outp = (float*)d_out;

    const int* row = eidx;
    const int* col = eidx + EE;

    float *A, *B, *C, *HH, *D, *Wp1, *W3, *b3;
    cudaGetSymbolAddress((void**)&A,   g_A);
    cudaGetSymbolAddress((void**)&B,   g_B);
    cudaGetSymbolAddress((void**)&C,   g_C);
    cudaGetSymbolAddress((void**)&HH,  g_HH);
    cudaGetSymbolAddress((void**)&D,   g_D);
    cudaGetSymbolAddress((void**)&Wp1, g_Wp1);
    cudaGetSymbolAddress((void**)&W3,  g_W3);
    cudaGetSymbolAddress((void**)&b3,  g_b3);

    // side stream + fork/join events (created once; resources, not cached work)
    static cudaStream_t s2 = nullptr;
    static cudaEvent_t  evFork = nullptr, evJoin = nullptr;
    if (s2 == nullptr) {
        cudaStreamCreateWithFlags(&s2, cudaStreamNonBlocking);
        cudaEventCreateWithFlags(&evFork, cudaEventDisableTiming);
        cudaEventCreateWithFlags(&evJoin, cudaEventDisableTiming);
    }

    const int TB = 256;
    const int nblkE2 = (EE / 2 + TB - 1) / TB;         // 1563
    const int nblkW  = (NN * 32 + TB - 1) / TB;        // 6250 (warp per node)
    const int gR = (NN + 127) / 128;                   // 391 row tiles

    // ---- fork: weights+gemm128 on s2, graph build on main stream ----
    cudaEventRecord(evFork, 0);
    cudaStreamWaitEvent(s2, evFork, 0);

    initW_kernel<<<(16384 + 64 * 80 + 80 + TB - 1) / TB, TB, 0, s2>>>(w1i, w1r, w2i, w2d, w2r, b2);
    gemm128_kernel<<<gR, TB, 0, s2>>>(x, Wp1, b1, A, NN);
    cudaEventRecord(evJoin, s2);

    initD_kernel<<<(NN + TB - 1) / TB, TB>>>();
    hist_kernel<<<nblkE2, TB>>>(col);
    scan_kernel<<<1, 1024>>>();
    fill_kernel<<<nblkE2, TB>>>(row, col);

    cudaStreamWaitEvent(0, evJoin, 0);   // join before first propagate

    // ---- conv1 ----
    prop64_kernel<false><<<nblkW, TB>>>(A, 128, A + 64, 128, B, 64);
    gemm_diag_kernel<<<dim3(gR, 2), TB>>>(B, w1d, C, NN);
    prop64_kernel<true><<<nblkW, TB>>>(C, 64, A + 64, 128, HH + 32, 64);   // H -> cols 32..63

    // ---- conv2 (algebraically folded) ----
    prop32_kernel<<<nblkW, TB>>>(HH + 32, 64, HH, 64);                     // PH -> cols 0..31
    gemm32_kernel<<<dim3(gR, 3), TB>>>(HH, 64, W3, 80, b3, D, 80, NN, 64, 80);
    prop40_kernel<<<nblkW, TB>>>(D, 80, D + 40, 80, outp);
}